// round 11
// baseline (speedup 1.0000x reference)
#include <cuda_runtime.h>
#include <cstdint>

typedef uint32_t u32;

#define SQ 1024   // sequence length
#define CC 256    // QDIM == KDIM
#define EE 512    // EMBED
#define BB 8      // batch
#define HH 8      // heads
#define DD 64     // head dim

__device__ float g_Q[BB * EE * SQ];
__device__ float g_K[BB * EE * SQ];
__device__ float g_V[BB * EE * SQ];
// tf32-preconverted inputs for the projection GEMM
__device__ float g_Xq[BB * CC * SQ];
__device__ float g_Xk[BB * CC * SQ];
__device__ float g_Wc[3 * EE * CC];

__device__ __forceinline__ unsigned tf32c(float x) {
    unsigned r; asm("cvt.rna.tf32.f32 %0,%1;" : "=r"(r) : "f"(x)); return r;
}
__device__ __forceinline__ float tf32f(float x) { return __uint_as_float(tf32c(x)); }
__device__ __forceinline__ float ex2f(float x) {
    float r; asm("ex2.approx.ftz.f32 %0,%1;" : "=f"(r) : "f"(x)); return r;
}
__device__ __forceinline__ void mma_tf32(
    float& c0, float& c1, float& c2, float& c3,
    unsigned a0, unsigned a1, unsigned a2, unsigned a3,
    unsigned b0, unsigned b1)
{
    asm volatile(
        "mma.sync.aligned.m16n8k8.row.col.f32.tf32.tf32.f32 "
        "{%0,%1,%2,%3},{%4,%5,%6,%7},{%8,%9},{%0,%1,%2,%3};"
        : "+f"(c0), "+f"(c1), "+f"(c2), "+f"(c3)
        : "r"(a0), "r"(a1), "r"(a2), "r"(a3), "r"(b0), "r"(b1));
}
__device__ __forceinline__ u32 smem_u32(const void* p) {
    u32 a;
    asm("{ .reg .u64 t; cvta.to.shared.u64 t, %1; cvt.u32.u64 %0, t; }"
        : "=r"(a) : "l"(p));
    return a;
}
__device__ __forceinline__ void cpa16(u32 dst, const void* src) {
    asm volatile("cp.async.cg.shared.global [%0], [%1], 16;"
                 :: "r"(dst), "l"(src) : "memory");
}
#define CP_COMMIT() asm volatile("cp.async.commit_group;" ::: "memory")
#define CP_WAIT(n)  asm volatile("cp.async.wait_group %0;" :: "n"(n) : "memory")

// ---------------------------------------------------------------------------
// Prep: tf32-round X (both inputs) and W into scratch (one-time, ~6us)
// ---------------------------------------------------------------------------
#define X4 (BB * CC * SQ / 4)     // 524288 float4 per input
#define W4 (3 * EE * CC / 4)      // 98304 float4
__global__ __launch_bounds__(256) void prep_kernel(
    const float* __restrict__ q_in, const float* __restrict__ k_in,
    const float* __restrict__ wq, const float* __restrict__ wk,
    const float* __restrict__ wv)
{
    int t = blockIdx.x * 256 + threadIdx.x;
    const float4* src;
    float4* dst;
    if (t < X4) {
        src = (const float4*)q_in + t;       dst = (float4*)g_Xq + t;
    } else if (t < 2 * X4) {
        src = (const float4*)k_in + (t - X4); dst = (float4*)g_Xk + (t - X4);
    } else if (t < 2 * X4 + W4) {
        int w = t - 2 * X4;
        int per = EE * CC / 4;
        const float* ws = (w < per) ? wq : (w < 2 * per ? wk : wv);
        src = (const float4*)ws + (w % per);  dst = (float4*)g_Wc + w;
    } else return;
    float4 v = *src;
    *dst = make_float4(tf32f(v.x), tf32f(v.y), tf32f(v.z), tf32f(v.w));
}

// ---------------------------------------------------------------------------
// Projection: Y[e][s] = tf32(W[e][c] X[c][s] + bias[e]) [Q pre-scaled].
// cp.async double-buffered, inputs already tf32 bits -> raw copies.
// ---------------------------------------------------------------------------
__global__ __launch_bounds__(256, 2) void proj_kernel(
    const float* __restrict__ biasq, const float* __restrict__ biask,
    const float* __restrict__ biasv)
{
    const int z = blockIdx.z;
    const int b = z / 3;
    const int p = z % 3;
    const float* X    = (p == 0 ? g_Xq : g_Xk) + (size_t)b * CC * SQ;
    const float* W    = g_Wc + (size_t)p * EE * CC;
    const float* bias = (p == 0) ? biasq : (p == 1 ? biask : biasv);
    float* Y = (p == 0 ? g_Q : (p == 1 ? g_K : g_V)) + (size_t)b * EE * SQ;
    const float oscale = (p == 0) ? 0.125f * 1.4426950408889634f : 1.0f;

    const int m0 = blockIdx.y * 128;
    const int n0 = blockIdx.x * 128;

    __shared__ __align__(16) float Ws[2][128 * 36];
    __shared__ __align__(16) float Xs[2][32 * 136];
    const u32 smW = smem_u32(Ws);
    const u32 smX = smem_u32(Xs);

    const int tid  = threadIdx.x;
    const int lane = tid & 31;
    const int wid  = tid >> 5;
    const int mw   = (wid & 1) * 64;
    const int nw   = (wid >> 1) * 32;
    const int r    = lane >> 2;
    const int l    = lane & 3;

    auto stage = [&](int buf, int k0) {
        #pragma unroll
        for (int rr = 0; rr < 4; rr++) {
            int idx = tid + rr * 256;
            int row = idx >> 3, kc = (idx & 7) * 4;        // W: 128 rows x 8 chunks
            cpa16(smW + (u32)(buf * (128 * 36) + row * 36 + kc) * 4u,
                  W + (size_t)(m0 + row) * CC + k0 + kc);
            int kx = idx >> 5, nc = (idx & 31) * 4;        // X: 32 rows x 32 chunks
            cpa16(smX + (u32)(buf * (32 * 136) + kx * 136 + nc) * 4u,
                  X + (size_t)(k0 + kx) * SQ + n0 + nc);
        }
        CP_COMMIT();
    };

    float c[4][4][4];
    #pragma unroll
    for (int mt = 0; mt < 4; mt++)
        #pragma unroll
        for (int nt = 0; nt < 4; nt++)
            #pragma unroll
            for (int e = 0; e < 4; e++) c[mt][nt][e] = 0.0f;

    stage(0, 0);
    int buf = 0;
    for (int k0 = 0; k0 < CC; k0 += 32) {
        if (k0 + 32 < CC) stage(buf ^ 1, k0 + 32);
        if (k0 + 32 < CC) { CP_WAIT(1); } else { CP_WAIT(0); }
        __syncthreads();

        const float* Wb = Ws[buf];
        const float* Xb = Xs[buf];
        #pragma unroll
        for (int ks = 0; ks < 4; ks++) {
            unsigned a[4][4];
            #pragma unroll
            for (int mt = 0; mt < 4; mt++) {
                const float* ap = Wb + (mw + mt * 16 + r) * 36 + ks * 8 + l;
                a[mt][0] = __float_as_uint(ap[0]);
                a[mt][1] = __float_as_uint(ap[8 * 36]);
                a[mt][2] = __float_as_uint(ap[4]);
                a[mt][3] = __float_as_uint(ap[8 * 36 + 4]);
            }
            #pragma unroll
            for (int nt = 0; nt < 4; nt++) {
                const float* bp = Xb + (ks * 8 + l) * 136 + nw + nt * 8 + r;
                unsigned b0 = __float_as_uint(bp[0]);
                unsigned b1 = __float_as_uint(bp[4 * 136]);
                #pragma unroll
                for (int mt = 0; mt < 4; mt++)
                    mma_tf32(c[mt][nt][0], c[mt][nt][1], c[mt][nt][2], c[mt][nt][3],
                             a[mt][0], a[mt][1], a[mt][2], a[mt][3], b0, b1);
            }
        }
        __syncthreads();
        buf ^= 1;
    }

    #pragma unroll
    for (int mt = 0; mt < 4; mt++) {
        int e0 = m0 + mw + mt * 16 + r;
        float bv0 = __ldg(bias + e0);
        float bv1 = __ldg(bias + e0 + 8);
        #pragma unroll
        for (int nt = 0; nt < 4; nt++) {
            int s = n0 + nw + nt * 8 + 2 * l;
            *(float2*)(Y + (size_t)e0 * SQ + s) =
                make_float2(tf32f((c[mt][nt][0] + bv0) * oscale),
                            tf32f((c[mt][nt][1] + bv0) * oscale));
            *(float2*)(Y + (size_t)(e0 + 8) * SQ + s) =
                make_float2(tf32f((c[mt][nt][2] + bv1) * oscale),
                            tf32f((c[mt][nt][3] + bv1) * oscale));
        }
    }
}

// ---------------------------------------------------------------------------
// Causal flash attention, tf32 mma, cp.async pipelined staging.
// Br=Bc=128, 256 threads, 8 warps x 16 query rows.
// K double-buffered. Wait choreography keeps K(kb+1) in flight through PV.
// ---------------------------------------------------------------------------
#define QKP 136
#define VPP 132
#define QS_F 0
#define KS_F 8704
#define VS_F 26112
#define PS_F 34560

__global__ __launch_bounds__(256, 1) void attn_kernel(float* __restrict__ out)
{
    extern __shared__ float smf[];
    const u32 smb = smem_u32(smf);
    float* Qs = smf + QS_F;
    float* Vs = smf + VS_F;
    float* Ps = smf + PS_F;

    const int qb = 7 - (int)blockIdx.x;  // heavy blocks first
    const int h  = blockIdx.y;
    const int b  = blockIdx.z;

    const float* Qg = g_Q + ((size_t)b * EE + h * DD) * SQ;  // tf32+scaled
    const float* Kg = g_K + ((size_t)b * EE + h * DD) * SQ;
    const float* Vg = g_V + ((size_t)b * EE + h * DD) * SQ;
    float*       Og = out + ((size_t)b * EE + h * DD) * SQ;

    const int s0   = qb * 128;
    const int tid  = threadIdx.x;
    const int lane = tid & 31;
    const int wid  = tid >> 5;
    const int r    = lane >> 2;
    const int l    = lane & 3;
    const int ib   = wid * 16;

    auto stage = [&](int base_f, int rowstride_f, const float* gsrc) {
        #pragma unroll
        for (int k2 = 0; k2 < 8; k2++) {
            int cch = tid + k2 * 256;
            int d = cch >> 5, o16 = cch & 31;
            u32 dst = smb + (u32)(base_f + d * rowstride_f + o16 * 4) * 4u;
            cpa16(dst, gsrc + (size_t)d * SQ + o16 * 4);
        }
    };

    // ---- prologue: Q + K(0) in one group
    stage(QS_F, QKP, Qg + s0);
    stage(KS_F, QKP, Kg);
    CP_COMMIT();

    float o[8][4];
    #pragma unroll
    for (int nt = 0; nt < 8; nt++)
        #pragma unroll
        for (int e = 0; e < 4; e++) o[nt][e] = 0.0f;
    float m0r = -1e30f, m1r = -1e30f, l0r = 0.0f, l1r = 0.0f;

    for (int kb = 0; kb <= qb; kb++) {
        const int c0 = kb * 128;
        __syncthreads();   // prev iter PV reads of Vs / Ks[(kb+1)&1] done

        // ---- issue V(kb), then K(kb+1): groups [K(kb), V(kb), K(kb+1)]
        stage(VS_F, VPP, Vg + c0);
        CP_COMMIT();
        if (kb < qb) {
            stage(KS_F + ((kb + 1) & 1) * 8704, QKP, Kg + c0 + 128);
            CP_COMMIT();
        }
        // wait K(kb) only (leave V(kb) and K(kb+1) in flight)
        if (kb < qb) { CP_WAIT(2); } else { CP_WAIT(1); }
        __syncthreads();

        const float* Ks = smf + KS_F + (kb & 1) * 8704;

        // ---- QK^T: 16 rows x 128 cols per warp
        float sc[16][4];
        #pragma unroll
        for (int nt = 0; nt < 16; nt++)
            #pragma unroll
            for (int e = 0; e < 4; e++) sc[nt][e] = 0.0f;

        #pragma unroll
        for (int ks = 0; ks < 8; ks++) {
            const float* ap = Qs + (ks * 8 + l) * QKP + ib + r;
            unsigned a0 = __float_as_uint(ap[0]);
            unsigned a1 = __float_as_uint(ap[8]);
            unsigned a2 = __float_as_uint(ap[4 * QKP]);
            unsigned a3 = __float_as_uint(ap[4 * QKP + 8]);
            #pragma unroll
            for (int nt = 0; nt < 16; nt++) {
                const float* bp = Ks + (ks * 8 + l) * QKP + nt * 8 + r;
                unsigned b0 = __float_as_uint(bp[0]);
                unsigned b1 = __float_as_uint(bp[4 * QKP]);
                mma_tf32(sc[nt][0], sc[nt][1], sc[nt][2], sc[nt][3],
                         a0, a1, a2, a3, b0, b1);
            }
        }

        // ---- causal mask on the diagonal block
        if (kb == qb) {
            const int il0 = s0 + ib + r, il1 = il0 + 8;
            #pragma unroll
            for (int nt = 0; nt < 16; nt++) {
                int j = c0 + nt * 8 + 2 * l;
                if (j     > il0) sc[nt][0] = -1e30f;
                if (j + 1 > il0) sc[nt][1] = -1e30f;
                if (j     > il1) sc[nt][2] = -1e30f;
                if (j + 1 > il1) sc[nt][3] = -1e30f;
            }
        }

        // ---- online softmax (rows live in a quad: shfl xor 1,2)
        float mx0 = -1e30f, mx1 = -1e30f;
        #pragma unroll
        for (int nt = 0; nt < 16; nt++) {
            mx0 = fmaxf(mx0, fmaxf(sc[nt][0], sc[nt][1]));
            mx1 = fmaxf(mx1, fmaxf(sc[nt][2], sc[nt][3]));
        }
        mx0 = fmaxf(mx0, __shfl_xor_sync(0xffffffffu, mx0, 1));
        mx0 = fmaxf(mx0, __shfl_xor_sync(0xffffffffu, mx0, 2));
        mx1 = fmaxf(mx1, __shfl_xor_sync(0xffffffffu, mx1, 1));
        mx1 = fmaxf(mx1, __shfl_xor_sync(0xffffffffu, mx1, 2));
        float mn0 = fmaxf(m0r, mx0), mn1 = fmaxf(m1r, mx1);
        float corr0 = ex2f(m0r - mn0), corr1 = ex2f(m1r - mn1);
        m0r = mn0; m1r = mn1;

        float rs0 = 0.0f, rs1 = 0.0f;
        #pragma unroll
        for (int nt = 0; nt < 16; nt++) {
            sc[nt][0] = ex2f(sc[nt][0] - mn0); rs0 += sc[nt][0];
            sc[nt][1] = ex2f(sc[nt][1] - mn0); rs0 += sc[nt][1];
            sc[nt][2] = ex2f(sc[nt][2] - mn1); rs1 += sc[nt][2];
            sc[nt][3] = ex2f(sc[nt][3] - mn1); rs1 += sc[nt][3];
        }
        rs0 += __shfl_xor_sync(0xffffffffu, rs0, 1);
        rs0 += __shfl_xor_sync(0xffffffffu, rs0, 2);
        rs1 += __shfl_xor_sync(0xffffffffu, rs1, 1);
        rs1 += __shfl_xor_sync(0xffffffffu, rs1, 2);
        l0r = l0r * corr0 + rs0;
        l1r = l1r * corr1 + rs1;

        // ---- P -> smem (tf32), warp-local rows
        #pragma unroll
        for (int nt = 0; nt < 16; nt++) {
            int jo = nt * 8 + 2 * l;
            *(float2*)(Ps + (ib + r) * VPP + jo) =
                make_float2(tf32f(sc[nt][0]), tf32f(sc[nt][1]));
            *(float2*)(Ps + (ib + r + 8) * VPP + jo) =
                make_float2(tf32f(sc[nt][2]), tf32f(sc[nt][3]));
        }
        __syncwarp();

        // ---- rescale O accumulators
        #pragma unroll
        for (int nt = 0; nt < 8; nt++) {
            o[nt][0] *= corr0; o[nt][1] *= corr0;
            o[nt][2] *= corr1; o[nt][3] *= corr1;
        }

        // ---- wait V(kb) only (K(kb+1) stays in flight), then PV
        if (kb < qb) { CP_WAIT(1); } else { CP_WAIT(0); }
        __syncthreads();

        #pragma unroll
        for (int ks = 0; ks < 16; ks++) {
            const float* ap = Ps + (ib + r) * VPP + ks * 8 + l;
            unsigned a0 = __float_as_uint(ap[0]);
            unsigned a1 = __float_as_uint(ap[8 * VPP]);
            unsigned a2 = __float_as_uint(ap[4]);
            unsigned a3 = __float_as_uint(ap[8 * VPP + 4]);
            #pragma unroll
            for (int nt = 0; nt < 8; nt++) {
                const float* bp = Vs + (nt * 8 + r) * VPP + ks * 8 + l;
                unsigned b0 = __float_as_uint(bp[0]);
                unsigned b1 = __float_as_uint(bp[4]);
                mma_tf32(o[nt][0], o[nt][1], o[nt][2], o[nt][3],
                         a0, a1, a2, a3, b0, b1);
            }
        }
    }

    // ---- epilogue: normalize, stage O as [i][d] (pad 68) in Ps, coalesced STG
    float inv0 = 1.0f / l0r, inv1 = 1.0f / l1r;
    __syncthreads();
    #pragma unroll
    for (int nt = 0; nt < 8; nt++) {
        int d = nt * 8 + 2 * l;
        float* p0 = Ps + (ib + r) * 68 + d;
        float* p1 = Ps + (ib + r + 8) * 68 + d;
        p0[0] = o[nt][0] * inv0; p0[1] = o[nt][1] * inv0;
        p1[0] = o[nt][2] * inv1; p1[1] = o[nt][3] * inv1;
    }
    __syncthreads();

    const int dcol = tid & 63;
    const int ibk  = tid >> 6;
    #pragma unroll
    for (int g = 0; g < 8; g++) {
        int i4 = ibk * 32 + g * 4;
        float4 w;
        w.x = Ps[(i4 + 0) * 68 + dcol];
        w.y = Ps[(i4 + 1) * 68 + dcol];
        w.z = Ps[(i4 + 2) * 68 + dcol];
        w.w = Ps[(i4 + 3) * 68 + dcol];
        *(float4*)(Og + (size_t)dcol * SQ + s0 + i4) = w;
    }
}

// ---------------------------------------------------------------------------
extern "C" void kernel_launch(void* const* d_in, const int* in_sizes, int n_in,
                              void* d_out, int out_size)
{
    const float* query = (const float*)d_in[0];
    const float* key   = (const float*)d_in[1];
    const float* Wq    = (const float*)d_in[2];
    const float* bq    = (const float*)d_in[3];
    const float* Wk    = (const float*)d_in[4];
    const float* bk    = (const float*)d_in[5];
    const float* Wv    = (const float*)d_in[6];
    const float* bv    = (const float*)d_in[7];

    const int total4 = 2 * X4 + W4;
    prep_kernel<<<(total4 + 255) / 256, 256>>>(query, key, Wq, Wk, Wv);

    dim3 g1(SQ / 128, EE / 128, BB * 3);
    proj_kernel<<<g1, 256>>>(bq, bk, bv);

    const int attn_smem = (PS_F + 128 * VPP) * 4;  // 205,824 B
    cudaFuncSetAttribute(attn_kernel,
                         cudaFuncAttributeMaxDynamicSharedMemorySize, attn_smem);
    dim3 g2(8, HH, BB);
    attn_kernel<<<g2, 256, attn_smem>>>((float*)d_out);
}